// round 4
// baseline (speedup 1.0000x reference)
#include <cuda_runtime.h>
#include <math.h>

#define B     40000
#define D     128
#define D4    (D/4)
#define ND    200000
#define ESUB  320000
#define ESUP  1280000

// Scratch (static device globals — no allocation in kernel_launch)
__device__ float g_diff[(size_t)B * D];
__device__ float g_dots[3];            // [0]=sum(in*old), [1]=sum(in^2), [2]=sum(old^2)
__device__ unsigned int g_ticket = 0;  // last-block-done counter

// ---------------------------------------------------------------------------
// Gather old rows, compute diff into g_diff, accumulate the three dot
// products, and have the LAST block finalize sim into out[B*D] and reset
// the accumulators (so every graph replay starts clean).
__global__ void gather_diff_dot_kernel(const float* __restrict__ inputs,
                                       const float* __restrict__ old_act,
                                       const int*   __restrict__ fields,
                                       float*       __restrict__ out,
                                       int out_size) {
    __shared__ float s_red[3][8];
    const int tid   = blockIdx.x * blockDim.x + threadIdx.x;
    const int nthr  = gridDim.x * blockDim.x;
    const int total = B * D4;

    float dot = 0.0f, nin = 0.0f, nold = 0.0f;

    const float4* in4  = (const float4*)inputs;
    const float4* old4 = (const float4*)old_act;
    float4*       df4  = (float4*)g_diff;

    for (int i = tid; i < total; i += nthr) {
        const int row = i >> 5;           // D4 == 32
        const int c4  = i & 31;
        const int f   = __ldg(&fields[row]);
        float4 a = in4[i];
        float4 o = old4[(size_t)f * D4 + c4];
        float4 d;
        d.x = a.x - o.x; d.y = a.y - o.y; d.z = a.z - o.z; d.w = a.w - o.w;
        df4[i] = d;
        dot  += a.x*o.x + a.y*o.y + a.z*o.z + a.w*o.w;
        nin  += a.x*a.x + a.y*a.y + a.z*a.z + a.w*a.w;
        nold += o.x*o.x + o.y*o.y + o.z*o.z + o.w*o.w;
    }

    #pragma unroll
    for (int off = 16; off > 0; off >>= 1) {
        dot  += __shfl_down_sync(0xffffffffu, dot,  off);
        nin  += __shfl_down_sync(0xffffffffu, nin,  off);
        nold += __shfl_down_sync(0xffffffffu, nold, off);
    }
    const int lane = threadIdx.x & 31;
    const int wid  = threadIdx.x >> 5;
    if (lane == 0) { s_red[0][wid] = dot; s_red[1][wid] = nin; s_red[2][wid] = nold; }
    __syncthreads();
    if (wid == 0) {
        const int nw = blockDim.x >> 5;
        float v0 = (lane < nw) ? s_red[0][lane] : 0.0f;
        float v1 = (lane < nw) ? s_red[1][lane] : 0.0f;
        float v2 = (lane < nw) ? s_red[2][lane] : 0.0f;
        #pragma unroll
        for (int off = 16; off > 0; off >>= 1) {
            v0 += __shfl_down_sync(0xffffffffu, v0, off);
            v1 += __shfl_down_sync(0xffffffffu, v1, off);
            v2 += __shfl_down_sync(0xffffffffu, v2, off);
        }
        if (lane == 0) {
            atomicAdd(&g_dots[0], v0);
            atomicAdd(&g_dots[1], v1);
            atomicAdd(&g_dots[2], v2);
            __threadfence();
            unsigned int t = atomicInc(&g_ticket, 0xffffffffu);
            if (t == gridDim.x - 1) {
                // last block: all partials are visible
                volatile float* vd = g_dots;
                float s0 = vd[0], s1 = vd[1], s2 = vd[2];
                if (out_size > B * D)
                    out[B * D] = s0 / (sqrtf(s1) * sqrtf(s2));
                vd[0] = 0.0f; vd[1] = 0.0f; vd[2] = 0.0f;
                g_ticket = 0;     // atomicInc wrapped it implicitly only at max; reset explicitly
            }
        }
    }
}

// ---------------------------------------------------------------------------
// Fused COO SpMM scatter over both edge lists, 4-way unrolled grid-stride.
// One warp per edge; 32 lanes x float4 cover the 128-float row.
// Batch 4 independent edges per iteration -> 4 LDG.128 in flight per warp.
__global__ void __launch_bounds__(256) spmm_fused_kernel(
        const int*   __restrict__ sub_rows,
        const int*   __restrict__ sub_cols,
        const float* __restrict__ sub_vals,
        const int*   __restrict__ sup_rows,
        const int*   __restrict__ sup_cols,
        const float* __restrict__ sup_vals,
        const float* __restrict__ old_act,
        float*       __restrict__ out) {
    const int lane   = threadIdx.x & 31;
    const int gwarp  = (blockIdx.x * blockDim.x + threadIdx.x) >> 5;
    const int stride = (gridDim.x * blockDim.x) >> 5;
    const int total  = ESUB + ESUP;

    int e = gwarp;
    for (; e + 3 * stride < total; e += 4 * stride) {
        int   r[4], c[4];
        float v[4];
        const float* __restrict__ src[4];

        #pragma unroll
        for (int k = 0; k < 4; k++) {
            const int ek = e + k * stride;
            const bool is_sub = (ek < ESUB);
            const int* rp   = is_sub ? sub_rows : (sup_rows - ESUB);
            const int* cp   = is_sub ? sub_cols : (sup_cols - ESUB);
            const float* vp = is_sub ? sub_vals : (sup_vals - ESUB);
            r[k]   = __ldg(rp + ek);
            c[k]   = __ldg(cp + ek);
            v[k]   = __ldg(vp + ek);
            src[k] = is_sub ? g_diff : old_act;
        }

        float4 s[4];
        #pragma unroll
        for (int k = 0; k < 4; k++)
            s[k] = ((const float4*)(src[k] + (size_t)c[k] * D))[lane];

        #pragma unroll
        for (int k = 0; k < 4; k++) {
            float4 x;
            x.x = s[k].x * v[k]; x.y = s[k].y * v[k];
            x.z = s[k].z * v[k]; x.w = s[k].w * v[k];
            float* o = out + (size_t)r[k] * D + lane * 4;
            asm volatile("red.global.add.v4.f32 [%0], {%1, %2, %3, %4};"
                         :: "l"(o), "f"(x.x), "f"(x.y), "f"(x.z), "f"(x.w)
                         : "memory");
        }
    }

    for (; e < total; e += stride) {
        const bool is_sub = (e < ESUB);
        const int* rp   = is_sub ? sub_rows : (sup_rows - ESUB);
        const int* cp   = is_sub ? sub_cols : (sup_cols - ESUB);
        const float* vp = is_sub ? sub_vals : (sup_vals - ESUB);
        const float* __restrict__ src = is_sub ? g_diff : old_act;
        const int   rr = __ldg(rp + e);
        const int   cc = __ldg(cp + e);
        const float vv = __ldg(vp + e);
        const float4 ss = ((const float4*)(src + (size_t)cc * D))[lane];
        float4 x;
        x.x = ss.x * vv; x.y = ss.y * vv; x.z = ss.z * vv; x.w = ss.w * vv;
        float* o = out + (size_t)rr * D + lane * 4;
        asm volatile("red.global.add.v4.f32 [%0], {%1, %2, %3, %4};"
                     :: "l"(o), "f"(x.x), "f"(x.y), "f"(x.z), "f"(x.w)
                     : "memory");
    }
}

// ---------------------------------------------------------------------------
extern "C" void kernel_launch(void* const* d_in, const int* in_sizes, int n_in,
                              void* d_out, int out_size) {
    const float* inputs   = (const float*)d_in[0];   // [B, D]
    const float* old_act  = (const float*)d_in[1];   // [ND, D]
    const int*   fields   = (const int*)  d_in[2];   // [B]
    const int*   sub_rows = (const int*)  d_in[3];   // [ESUB]
    const int*   sub_cols = (const int*)  d_in[4];
    const float* sub_vals = (const float*)d_in[5];
    const int*   sup_rows = (const int*)  d_in[6];   // [ESUP]
    const int*   sup_cols = (const int*)  d_in[7];
    const float* sup_vals = (const float*)d_in[8];
    float* out = (float*)d_out;

    // Zero the accumulation region (first B*D elements of out).
    size_t zcount = (size_t)((out_size < B * D) ? out_size : B * D);
    cudaMemsetAsync(d_out, 0, zcount * sizeof(float));

    gather_diff_dot_kernel<<<2048, 256>>>(inputs, old_act, fields, out, out_size);

    // Fused SpMM: subsampled_support @ diff  +  support @ old_activation
    spmm_fused_kernel<<<148 * 16, 256>>>(sub_rows, sub_cols, sub_vals,
                                         sup_rows, sup_cols, sup_vals,
                                         old_act, out);
}

// round 5
// speedup vs baseline: 1.4319x; 1.4319x over previous
#include <cuda_runtime.h>
#include <math.h>

#define B     40000
#define D     128
#define D4    (D/4)
#define ND    200000
#define ESUB  320000
#define ESUP  1280000
#define SLOTS 128          // max edges per output row (mean 40, 14-sigma safe)

// Scratch (static device globals — no allocation in kernel_launch)
__device__ float g_diff[(size_t)B * D];
__device__ float g_dots[3];
__device__ unsigned int g_ticket = 0;
__device__ int  g_cnt[B];
__device__ int2 g_meta[(size_t)B * SLOTS];   // (col_tagged, val_bits)

// ---------------------------------------------------------------------------
__global__ void zero_cnt_kernel() {
    const int i = blockIdx.x * blockDim.x + threadIdx.x;
    if (i < B) g_cnt[i] = 0;
}

// ---------------------------------------------------------------------------
// Gather old rows, compute diff into g_diff, accumulate the three dot
// products; last block writes sim to out[B*D] and resets accumulators.
__global__ void gather_diff_dot_kernel(const float* __restrict__ inputs,
                                       const float* __restrict__ old_act,
                                       const int*   __restrict__ fields,
                                       float*       __restrict__ out,
                                       int out_size) {
    __shared__ float s_red[3][8];
    const int tid   = blockIdx.x * blockDim.x + threadIdx.x;
    const int nthr  = gridDim.x * blockDim.x;
    const int total = B * D4;

    float dot = 0.0f, nin = 0.0f, nold = 0.0f;

    const float4* in4  = (const float4*)inputs;
    const float4* old4 = (const float4*)old_act;
    float4*       df4  = (float4*)g_diff;

    for (int i = tid; i < total; i += nthr) {
        const int row = i >> 5;           // D4 == 32
        const int c4  = i & 31;
        const int f   = __ldg(&fields[row]);
        float4 a = in4[i];
        float4 o = old4[(size_t)f * D4 + c4];
        float4 d;
        d.x = a.x - o.x; d.y = a.y - o.y; d.z = a.z - o.z; d.w = a.w - o.w;
        df4[i] = d;
        dot  += a.x*o.x + a.y*o.y + a.z*o.z + a.w*o.w;
        nin  += a.x*a.x + a.y*a.y + a.z*a.z + a.w*a.w;
        nold += o.x*o.x + o.y*o.y + o.z*o.z + o.w*o.w;
    }

    #pragma unroll
    for (int off = 16; off > 0; off >>= 1) {
        dot  += __shfl_down_sync(0xffffffffu, dot,  off);
        nin  += __shfl_down_sync(0xffffffffu, nin,  off);
        nold += __shfl_down_sync(0xffffffffu, nold, off);
    }
    const int lane = threadIdx.x & 31;
    const int wid  = threadIdx.x >> 5;
    if (lane == 0) { s_red[0][wid] = dot; s_red[1][wid] = nin; s_red[2][wid] = nold; }
    __syncthreads();
    if (wid == 0) {
        const int nw = blockDim.x >> 5;
        float v0 = (lane < nw) ? s_red[0][lane] : 0.0f;
        float v1 = (lane < nw) ? s_red[1][lane] : 0.0f;
        float v2 = (lane < nw) ? s_red[2][lane] : 0.0f;
        #pragma unroll
        for (int off = 16; off > 0; off >>= 1) {
            v0 += __shfl_down_sync(0xffffffffu, v0, off);
            v1 += __shfl_down_sync(0xffffffffu, v1, off);
            v2 += __shfl_down_sync(0xffffffffu, v2, off);
        }
        if (lane == 0) {
            atomicAdd(&g_dots[0], v0);
            atomicAdd(&g_dots[1], v1);
            atomicAdd(&g_dots[2], v2);
            __threadfence();
            unsigned int t = atomicInc(&g_ticket, 0xffffffffu);
            if (t == gridDim.x - 1) {
                volatile float* vd = g_dots;
                float s0 = vd[0], s1 = vd[1], s2 = vd[2];
                if (out_size > B * D)
                    out[B * D] = s0 / (sqrtf(s1) * sqrtf(s2));
                vd[0] = 0.0f; vd[1] = 0.0f; vd[2] = 0.0f;
                g_ticket = 0;
            }
        }
    }
}

// ---------------------------------------------------------------------------
// Bucket-fill: scatter every edge (both matrices) into its output row's
// slot list. Columns of the sub matrix are tagged by +ND so the accumulate
// kernel knows to read g_diff instead of old_activation.
__global__ void __launch_bounds__(256) fill_kernel(
        const int*   __restrict__ sub_rows,
        const int*   __restrict__ sub_cols,
        const float* __restrict__ sub_vals,
        const int*   __restrict__ sup_rows,
        const int*   __restrict__ sup_cols,
        const float* __restrict__ sup_vals) {
    const int tid   = blockIdx.x * blockDim.x + threadIdx.x;
    const int nthr  = gridDim.x * blockDim.x;
    const int total = ESUB + ESUP;

    for (int e = tid; e < total; e += nthr) {
        int r, c; float v;
        if (e < ESUB) {
            r = __ldg(&sub_rows[e]);
            c = __ldg(&sub_cols[e]) + ND;   // tag: read from g_diff
            v = __ldg(&sub_vals[e]);
        } else {
            const int i = e - ESUB;
            r = __ldg(&sup_rows[i]);
            c = __ldg(&sup_cols[i]);
            v = __ldg(&sup_vals[i]);
        }
        const int pos = atomicAdd(&g_cnt[r], 1);
        if (pos < SLOTS) {
            int2 m; m.x = c; m.y = __float_as_int(v);
            g_meta[(size_t)r * SLOTS + pos] = m;
        }
    }
}

// ---------------------------------------------------------------------------
// Row accumulation: one warp per output row. Each lane holds a float4
// accumulator (32 lanes x 4 = 128 columns). Metadata is loaded
// lane-cooperatively and shuffle-broadcast; 4 independent source-row loads
// are kept in flight. Single coalesced float4 store per row — NO atomics.
__global__ void __launch_bounds__(256) accumulate_kernel(
        const float* __restrict__ old_act,
        float*       __restrict__ out) {
    const int lane = threadIdx.x & 31;
    const int row  = blockIdx.x * 8 + (threadIdx.x >> 5);
    if (row >= B) return;

    int deg = g_cnt[row];
    if (deg > SLOTS) deg = SLOTS;
    const size_t base = (size_t)row * SLOTS;

    float4 acc; acc.x = acc.y = acc.z = acc.w = 0.0f;

    for (int k0 = 0; k0 < deg; k0 += 32) {
        // lane-cooperative metadata load
        int   mc = 0;
        float mv = 0.0f;
        if (k0 + lane < deg) {
            int2 m = g_meta[base + k0 + lane];
            mc = m.x;
            mv = __int_as_float(m.y);
        }
        const int n = (deg - k0 < 32) ? (deg - k0) : 32;

        int k = 0;
        for (; k + 4 <= n; k += 4) {
            float4 s[4]; float vv[4];
            #pragma unroll
            for (int j = 0; j < 4; j++) {
                const int   c = __shfl_sync(0xffffffffu, mc, k + j);
                vv[j]         = __shfl_sync(0xffffffffu, mv, k + j);
                const float* src = (c < ND)
                    ? (old_act + (size_t)c * D)
                    : (g_diff + (size_t)(c - ND) * D);
                s[j] = ((const float4*)src)[lane];
            }
            #pragma unroll
            for (int j = 0; j < 4; j++) {
                acc.x += s[j].x * vv[j];
                acc.y += s[j].y * vv[j];
                acc.z += s[j].z * vv[j];
                acc.w += s[j].w * vv[j];
            }
        }
        for (; k < n; k++) {
            const int   c = __shfl_sync(0xffffffffu, mc, k);
            const float v = __shfl_sync(0xffffffffu, mv, k);
            const float* src = (c < ND)
                ? (old_act + (size_t)c * D)
                : (g_diff + (size_t)(c - ND) * D);
            const float4 s = ((const float4*)src)[lane];
            acc.x += s.x * v; acc.y += s.y * v;
            acc.z += s.z * v; acc.w += s.w * v;
        }
    }

    ((float4*)(out + (size_t)row * D))[lane] = acc;
}

// ---------------------------------------------------------------------------
extern "C" void kernel_launch(void* const* d_in, const int* in_sizes, int n_in,
                              void* d_out, int out_size) {
    const float* inputs   = (const float*)d_in[0];   // [B, D]
    const float* old_act  = (const float*)d_in[1];   // [ND, D]
    const int*   fields   = (const int*)  d_in[2];   // [B]
    const int*   sub_rows = (const int*)  d_in[3];   // [ESUB]
    const int*   sub_cols = (const int*)  d_in[4];
    const float* sub_vals = (const float*)d_in[5];
    const int*   sup_rows = (const int*)  d_in[6];   // [ESUP]
    const int*   sup_cols = (const int*)  d_in[7];
    const float* sup_vals = (const float*)d_in[8];
    float* out = (float*)d_out;

    // Reset per-row counters (graph-replay safe).
    zero_cnt_kernel<<<(B + 255) / 256, 256>>>();

    // Gather + diff + cosine similarity (writes out[B*D]).
    gather_diff_dot_kernel<<<2048, 256>>>(inputs, old_act, fields, out, out_size);

    // Bucket both edge lists by output row.
    fill_kernel<<<148 * 8, 256>>>(sub_rows, sub_cols, sub_vals,
                                  sup_rows, sup_cols, sup_vals);

    // Register-accumulated SpMM over the buckets. Fully writes out[0 .. B*D).
    accumulate_kernel<<<B / 8, 256>>>(old_act, out);
}

// round 6
// speedup vs baseline: 1.6302x; 1.1385x over previous
#include <cuda_runtime.h>
#include <cuda_fp16.h>
#include <math.h>

#define B     40000
#define D     128
#define D4    (D/4)
#define ND    200000
#define ESUB  320000
#define ESUP  1280000
#define SLOTS 128          // max edges per output row (mean 40, 14-sigma safe)

#define GA 512             // prep blocks: gather/diff/dot
#define GB 512             // prep blocks: old_act fp16 convert
#define GC 512             // prep blocks: bucket fill
#define PREP_GRID (GA + GB + GC)

// Scratch (static device globals — no allocation in kernel_launch)
__device__ __half g_old_h[(size_t)ND * D];   // 51.2 MB
__device__ __half g_diff_h[(size_t)B * D];   // 10.2 MB
__device__ float g_dots[3];
__device__ unsigned int g_ticket = 0;
__device__ int  g_cnt[B];
__device__ int2 g_meta[(size_t)B * SLOTS];   // (col_tagged, val_bits)

// ---------------------------------------------------------------------------
// Fused prep kernel. Section by blockIdx.x % 3 so the three workloads
// (latency-bound gather, DRAM-streaming convert, atomic-bound fill)
// overlap on the SM array.
__global__ void __launch_bounds__(256) prep_kernel(
        const float* __restrict__ inputs,
        const float* __restrict__ old_act,
        const int*   __restrict__ fields,
        const int*   __restrict__ sub_rows,
        const int*   __restrict__ sub_cols,
        const float* __restrict__ sub_vals,
        const int*   __restrict__ sup_rows,
        const int*   __restrict__ sup_cols,
        const float* __restrict__ sup_vals,
        float*       __restrict__ out,
        int out_size) {
    const int sec = blockIdx.x % 3;
    const int sb  = blockIdx.x / 3;

    if (sec == 0) {
        // ---- Section A: gather old rows, diff (fp16), three dot products ----
        __shared__ float s_red[3][8];
        const int tid   = sb * blockDim.x + threadIdx.x;
        const int nthr  = GA * blockDim.x;
        const int total = B * D4;

        float dot = 0.0f, nin = 0.0f, nold = 0.0f;

        const float4* in4  = (const float4*)inputs;
        const float4* old4 = (const float4*)old_act;
        uint2*        df4  = (uint2*)g_diff_h;   // 4 halves per element

        for (int i = tid; i < total; i += nthr) {
            const int row = i >> 5;           // D4 == 32
            const int c4  = i & 31;
            const int f   = __ldg(&fields[row]);
            float4 a = in4[i];
            float4 o = old4[(size_t)f * D4 + c4];
            float4 d;
            d.x = a.x - o.x; d.y = a.y - o.y; d.z = a.z - o.z; d.w = a.w - o.w;
            __half2 lo = __floats2half2_rn(d.x, d.y);
            __half2 hi = __floats2half2_rn(d.z, d.w);
            uint2 packed;
            packed.x = *(const unsigned int*)&lo;
            packed.y = *(const unsigned int*)&hi;
            df4[i] = packed;
            dot  += a.x*o.x + a.y*o.y + a.z*o.z + a.w*o.w;
            nin  += a.x*a.x + a.y*a.y + a.z*a.z + a.w*a.w;
            nold += o.x*o.x + o.y*o.y + o.z*o.z + o.w*o.w;
        }

        #pragma unroll
        for (int off = 16; off > 0; off >>= 1) {
            dot  += __shfl_down_sync(0xffffffffu, dot,  off);
            nin  += __shfl_down_sync(0xffffffffu, nin,  off);
            nold += __shfl_down_sync(0xffffffffu, nold, off);
        }
        const int lane = threadIdx.x & 31;
        const int wid  = threadIdx.x >> 5;
        if (lane == 0) { s_red[0][wid] = dot; s_red[1][wid] = nin; s_red[2][wid] = nold; }
        __syncthreads();
        if (wid == 0) {
            const int nw = blockDim.x >> 5;
            float v0 = (lane < nw) ? s_red[0][lane] : 0.0f;
            float v1 = (lane < nw) ? s_red[1][lane] : 0.0f;
            float v2 = (lane < nw) ? s_red[2][lane] : 0.0f;
            #pragma unroll
            for (int off = 16; off > 0; off >>= 1) {
                v0 += __shfl_down_sync(0xffffffffu, v0, off);
                v1 += __shfl_down_sync(0xffffffffu, v1, off);
                v2 += __shfl_down_sync(0xffffffffu, v2, off);
            }
            if (lane == 0) {
                atomicAdd(&g_dots[0], v0);
                atomicAdd(&g_dots[1], v1);
                atomicAdd(&g_dots[2], v2);
                __threadfence();
                unsigned int t = atomicInc(&g_ticket, 0xffffffffu);
                if (t == GA - 1) {
                    volatile float* vd = g_dots;
                    float s0 = vd[0], s1 = vd[1], s2 = vd[2];
                    if (out_size > B * D)
                        out[B * D] = s0 / (sqrtf(s1) * sqrtf(s2));
                    vd[0] = 0.0f; vd[1] = 0.0f; vd[2] = 0.0f;
                    g_ticket = 0;
                }
            }
        }
    } else if (sec == 1) {
        // ---- Section B: convert old_activation -> fp16 (streaming) ----
        const int tid   = sb * blockDim.x + threadIdx.x;
        const int nthr  = GB * blockDim.x;
        const int total = (ND * D) / 8;      // 8 floats per item
        const float4* src = (const float4*)old_act;
        uint4*        dst = (uint4*)g_old_h;

        for (int i = tid; i < total; i += nthr) {
            float4 a = src[2 * i];
            float4 b = src[2 * i + 1];
            __half2 h0 = __floats2half2_rn(a.x, a.y);
            __half2 h1 = __floats2half2_rn(a.z, a.w);
            __half2 h2 = __floats2half2_rn(b.x, b.y);
            __half2 h3 = __floats2half2_rn(b.z, b.w);
            uint4 p;
            p.x = *(const unsigned int*)&h0;
            p.y = *(const unsigned int*)&h1;
            p.z = *(const unsigned int*)&h2;
            p.w = *(const unsigned int*)&h3;
            dst[i] = p;
        }
    } else {
        // ---- Section C: bucket-fill both edge lists by output row ----
        const int tid   = sb * blockDim.x + threadIdx.x;
        const int nthr  = GC * blockDim.x;
        const int total = ESUB + ESUP;

        for (int e = tid; e < total; e += nthr) {
            int r, c; float v;
            if (e < ESUB) {
                r = __ldg(&sub_rows[e]);
                c = __ldg(&sub_cols[e]) + ND;   // tag: read from g_diff_h
                v = __ldg(&sub_vals[e]);
            } else {
                const int i = e - ESUB;
                r = __ldg(&sup_rows[i]);
                c = __ldg(&sup_cols[i]);
                v = __ldg(&sup_vals[i]);
            }
            const int pos = atomicAdd(&g_cnt[r], 1);
            if (pos < SLOTS) {
                int2 m; m.x = c; m.y = __float_as_int(v);
                g_meta[(size_t)r * SLOTS + pos] = m;
            }
        }
    }
}

// ---------------------------------------------------------------------------
// Row accumulation: one warp per output row. Each lane holds a float4
// accumulator (32 lanes x 4 = 128 columns). Sources are fp16: 8B per lane.
// Metadata shuffle-broadcast; 4 independent row-loads in flight.
// Single coalesced float4 store per row — NO atomics, no prior memset needed.
__global__ void __launch_bounds__(256) accumulate_kernel(
        float* __restrict__ out) {
    const int lane = threadIdx.x & 31;
    const int row  = blockIdx.x * 8 + (threadIdx.x >> 5);
    if (row >= B) return;

    int deg = g_cnt[row];
    if (deg > SLOTS) deg = SLOTS;
    const size_t base = (size_t)row * SLOTS;

    float4 acc; acc.x = acc.y = acc.z = acc.w = 0.0f;

    for (int k0 = 0; k0 < deg; k0 += 32) {
        int   mc = 0;
        float mv = 0.0f;
        if (k0 + lane < deg) {
            int2 m = g_meta[base + k0 + lane];
            mc = m.x;
            mv = __int_as_float(m.y);
        }
        const int n = (deg - k0 < 32) ? (deg - k0) : 32;

        int k = 0;
        for (; k + 4 <= n; k += 4) {
            uint2 s[4]; float vv[4];
            #pragma unroll
            for (int j = 0; j < 4; j++) {
                const int c = __shfl_sync(0xffffffffu, mc, k + j);
                vv[j]       = __shfl_sync(0xffffffffu, mv, k + j);
                const __half* src = (c < ND)
                    ? (g_old_h  + (size_t)c * D)
                    : (g_diff_h + (size_t)(c - ND) * D);
                s[j] = ((const uint2*)src)[lane];
            }
            #pragma unroll
            for (int j = 0; j < 4; j++) {
                float2 f0 = __half22float2(*(const __half2*)&s[j].x);
                float2 f1 = __half22float2(*(const __half2*)&s[j].y);
                acc.x += f0.x * vv[j];
                acc.y += f0.y * vv[j];
                acc.z += f1.x * vv[j];
                acc.w += f1.y * vv[j];
            }
        }
        for (; k < n; k++) {
            const int   c = __shfl_sync(0xffffffffu, mc, k);
            const float v = __shfl_sync(0xffffffffu, mv, k);
            const __half* src = (c < ND)
                ? (g_old_h  + (size_t)c * D)
                : (g_diff_h + (size_t)(c - ND) * D);
            const uint2 s = ((const uint2*)src)[lane];
            float2 f0 = __half22float2(*(const __half2*)&s.x);
            float2 f1 = __half22float2(*(const __half2*)&s.y);
            acc.x += f0.x * v; acc.y += f0.y * v;
            acc.z += f1.x * v; acc.w += f1.y * v;
        }
    }

    ((float4*)(out + (size_t)row * D))[lane] = acc;
}

// ---------------------------------------------------------------------------
extern "C" void kernel_launch(void* const* d_in, const int* in_sizes, int n_in,
                              void* d_out, int out_size) {
    const float* inputs   = (const float*)d_in[0];   // [B, D]
    const float* old_act  = (const float*)d_in[1];   // [ND, D]
    const int*   fields   = (const int*)  d_in[2];   // [B]
    const int*   sub_rows = (const int*)  d_in[3];   // [ESUB]
    const int*   sub_cols = (const int*)  d_in[4];
    const float* sub_vals = (const float*)d_in[5];
    const int*   sup_rows = (const int*)  d_in[6];   // [ESUP]
    const int*   sup_cols = (const int*)  d_in[7];
    const float* sup_vals = (const float*)d_in[8];
    float* out = (float*)d_out;

    // Zero per-row counters (graph-replay safe) via memset node.
    void* cnt_ptr = nullptr;
    cudaGetSymbolAddress(&cnt_ptr, g_cnt);
    cudaMemsetAsync(cnt_ptr, 0, B * sizeof(int));

    // Zero only the tail of out beyond the accumulated region (accumulate
    // fully overwrites out[0 .. B*D); prep writes out[B*D]).
    if (out_size > B * D + 1) {
        cudaMemsetAsync(out + (B * D + 1), 0,
                        (size_t)(out_size - B * D - 1) * sizeof(float));
    }

    // Fused gather+convert+fill.
    prep_kernel<<<PREP_GRID, 256>>>(inputs, old_act, fields,
                                    sub_rows, sub_cols, sub_vals,
                                    sup_rows, sup_cols, sup_vals,
                                    out, out_size);

    // Register-accumulated SpMM over fp16 sources. Writes out[0 .. B*D).
    accumulate_kernel<<<B / 8, 256>>>(out);
}